// round 6
// baseline (speedup 1.0000x reference)
#include <cuda_runtime.h>
#include <cstdint>

#define NROWS 16384
#define DDIM  32
#define HDIM  128
#define BK    32                 // K floats per stage -> 128B rows
#define BN    40                 // 32 msg cols + degree(col32) + 7 pad -> 5 live n8-tiles
#define STAGES 8
#define NT    (NROWS / BK)       // 512
#define ABYTES (128 * 128)       // 16384
#define BBYTES (BN * 128)        // 5120
#define STAGE_BYTES (ABYTES + BBYTES)               // 21504
#define SMEM_TOTAL  (1024 + STAGES * STAGE_BYTES)   // 173056

// device scratch
__device__ float g_msgB[BN * NROWS];   // [col][k]; cols0-31 tf32 msg, col32=1, 33-39=0
__device__ float g_agg [NROWS * DDIM];

// ---------------- PTX helpers ----------------
__device__ __forceinline__ void cp16(uint32_t dst, const void* src) {
    asm volatile("cp.async.cg.shared.global [%0], [%1], 16;" :: "r"(dst), "l"(src) : "memory");
}
__device__ __forceinline__ float tf32_rna(float x) {
    uint32_t r;
    asm("cvt.rna.tf32.f32 %0, %1;" : "=r"(r) : "f"(x));
    return __uint_as_float(r);
}
__device__ __forceinline__ void ldsm_x4(uint32_t& r0, uint32_t& r1, uint32_t& r2, uint32_t& r3,
                                        uint32_t addr) {
    asm volatile("ldmatrix.sync.aligned.m8n8.x4.shared.b16 {%0,%1,%2,%3}, [%4];"
                 : "=r"(r0), "=r"(r1), "=r"(r2), "=r"(r3) : "r"(addr));
}
__device__ __forceinline__ void ldsm_x2(uint32_t& r0, uint32_t& r1, uint32_t addr) {
    asm volatile("ldmatrix.sync.aligned.m8n8.x2.shared.b16 {%0,%1}, [%2];"
                 : "=r"(r0), "=r"(r1) : "r"(addr));
}
__device__ __forceinline__ void mma_tf32(float* c, uint32_t a0, uint32_t a1,
                                         uint32_t a2, uint32_t a3,
                                         uint32_t b0, uint32_t b1) {
    asm volatile(
        "mma.sync.aligned.m16n8k8.row.col.f32.tf32.tf32.f32 "
        "{%0,%1,%2,%3}, {%4,%5,%6,%7}, {%8,%9}, {%0,%1,%2,%3};"
        : "+f"(c[0]), "+f"(c[1]), "+f"(c[2]), "+f"(c[3])
        : "r"(a0), "r"(a1), "r"(a2), "r"(a3), "r"(b0), "r"(b1));
}

// ==================== Kernel 1: message MLP (proven round-3 shape) ====================
__global__ __launch_bounds__(128) void msg_kernel(
    const float* __restrict__ states, const float* __restrict__ W1,
    const float* __restrict__ b1,     const float* __restrict__ W2,
    const float* __restrict__ b2)
{
    __shared__ float sW1[DDIM * HDIM];
    __shared__ float sW2[HDIM * DDIM];
    const int tid = threadIdx.x;
    for (int i = tid; i < DDIM * HDIM; i += 128) sW1[i] = W1[i];
    for (int i = tid; i < HDIM * DDIM; i += 128) sW2[i] = W2[i];
    __syncthreads();

    const int row = blockIdx.x * 128 + tid;
    float s[DDIM];
    const float4* sp = reinterpret_cast<const float4*>(states + (size_t)row * DDIM);
    #pragma unroll
    for (int j4 = 0; j4 < DDIM / 4; j4++) {
        float4 v = sp[j4];
        s[4*j4+0] = v.x; s[4*j4+1] = v.y; s[4*j4+2] = v.z; s[4*j4+3] = v.w;
    }
    float m[DDIM];
    #pragma unroll
    for (int d = 0; d < DDIM; d++) m[d] = __ldg(&b2[d]);

    #pragma unroll 2
    for (int hg = 0; hg < HDIM / 4; hg++) {
        float4 hid = __ldg(reinterpret_cast<const float4*>(b1) + hg);
        #pragma unroll
        for (int j = 0; j < DDIM; j++) {
            float4 w = *reinterpret_cast<const float4*>(&sW1[j * HDIM + 4 * hg]);
            hid.x += s[j] * w.x; hid.y += s[j] * w.y;
            hid.z += s[j] * w.z; hid.w += s[j] * w.w;
        }
        float rr[4] = {fmaxf(hid.x, 0.f), fmaxf(hid.y, 0.f),
                       fmaxf(hid.z, 0.f), fmaxf(hid.w, 0.f)};
        #pragma unroll
        for (int e = 0; e < 4; e++) {
            float r = rr[e];
            #pragma unroll
            for (int d4 = 0; d4 < DDIM / 4; d4++) {
                float4 w = *reinterpret_cast<const float4*>(&sW2[(4*hg+e) * DDIM + 4*d4]);
                m[4*d4+0] += r * w.x; m[4*d4+1] += r * w.y;
                m[4*d4+2] += r * w.z; m[4*d4+3] += r * w.w;
            }
        }
    }
    #pragma unroll
    for (int d = 0; d < DDIM; d++)
        g_msgB[(size_t)d * NROWS + row] = tf32_rna(m[d]);
    g_msgB[(size_t)32 * NROWS + row] = 1.0f;          // degree column
    #pragma unroll
    for (int d = 33; d < BN; d++)
        g_msgB[(size_t)d * NROWS + row] = 0.0f;       // pad
}

// ==================== Kernel 2: tf32 aggregation, 8 warps = 4 row-groups x 2 k-halves ====
__device__ __forceinline__ void fill_stage(const float* __restrict__ adj, size_t rowBase,
                                           int tile, uint32_t stage, int tid)
{
    const float* aSrc = adj + rowBase * NROWS + (size_t)tile * BK;
    #pragma unroll
    for (int i = 0; i < 4; i++) {                     // A: 1024 chunks / 256 thr
        int c = tid + 256 * i;
        int r = c >> 3, k4 = c & 7;
        uint32_t dst = stage + ((r * 8 + (k4 ^ (r & 7))) << 4);
        cp16(dst, aSrc + (size_t)r * NROWS + (k4 << 2));
    }
    {                                                 // B: 320 chunks
        int r = tid >> 3, k4 = tid & 7;
        uint32_t dst = stage + ABYTES + ((r * 8 + (k4 ^ (r & 7))) << 4);
        cp16(dst, g_msgB + (size_t)r * NROWS + (size_t)tile * BK + (k4 << 2));
        if (tid < 64) {
            int c = tid + 256;
            r = c >> 3; k4 = c & 7;
            dst = stage + ABYTES + ((r * 8 + (k4 ^ (r & 7))) << 4);
            cp16(dst, g_msgB + (size_t)r * NROWS + (size_t)tile * BK + (k4 << 2));
        }
    }
    asm volatile("cp.async.commit_group;" ::: "memory");
}

__global__ __launch_bounds__(256, 1) void agg_kernel(const float* __restrict__ adj)
{
    extern __shared__ char smem[];
    uint32_t sraw = (uint32_t)__cvta_generic_to_shared(smem);
    const uint32_t stage0 = (sraw + 1023u) & ~1023u;
    float* ex = reinterpret_cast<float*>(smem + (stage0 - sraw));  // reused post-loop

    const int tid  = threadIdx.x;
    const int wid  = tid >> 5;
    const int lane = tid & 31;
    const int wr   = wid & 3;        // row group: rows wr*32 .. wr*32+31
    const int kh   = wid >> 2;       // k-half: k-steps {0,1} or {2,3}
    const size_t rowBase = (size_t)blockIdx.x * 128;

    const int jm = lane >> 3;        // x4 matrix index 0..3
    const int qm = lane & 7;
    const int hb = jm & 1;           // x2 half select

    float acc[2][5][4];              // [m16 block][n-tile][frag], partial (k-half)
    #pragma unroll
    for (int mi = 0; mi < 2; mi++)
        #pragma unroll
        for (int t = 0; t < 5; t++)
            #pragma unroll
            for (int e = 0; e < 4; e++) acc[mi][t][e] = 0.f;

    for (int t = 0; t < STAGES - 1; t++)
        fill_stage(adj, rowBase, t, stage0 + t * STAGE_BYTES, tid);

    for (int kt = 0; kt < NT; kt++) {
        asm volatile("cp.async.wait_group %0;" :: "n"(STAGES - 2) : "memory");
        __syncthreads();

        const uint32_t sA = stage0 + (uint32_t)(kt & (STAGES - 1)) * STAGE_BYTES;
        const uint32_t sB = sA + ABYTES;

        #pragma unroll
        for (int s = 0; s < 2; s++) {
            const int sa  = kh * 2 + s;              // this warp's k-step
            const int ch  = 2 * sa + (jm & 1);
            const int chx = 2 * sa + hb;
            uint32_t b[10];
            {
                const int nr0 = (jm >> 1) * 8 + qm;            // tiles 0,1
                ldsm_x4(b[0], b[1], b[2], b[3],
                        sB + ((nr0 * 8 + (ch ^ (nr0 & 7))) << 4));
                const int nr1 = 16 + (jm >> 1) * 8 + qm;        // tiles 2,3
                ldsm_x4(b[4], b[5], b[6], b[7],
                        sB + ((nr1 * 8 + (ch ^ (nr1 & 7))) << 4));
                const int nr2 = 32 + qm;                        // tile 4 (degree)
                ldsm_x2(b[8], b[9], sB + ((nr2 * 8 + (chx ^ (nr2 & 7))) << 4));
            }
            #pragma unroll
            for (int mi = 0; mi < 2; mi++) {
                const int arow = wr * 32 + mi * 16 + (jm >> 1) * 8 + qm;
                uint32_t a0, a1, a2, a3;
                ldsm_x4(a0, a1, a2, a3, sA + ((arow * 8 + (ch ^ (arow & 7))) << 4));
                #pragma unroll
                for (int t = 0; t < 5; t++)
                    mma_tf32(acc[mi][t], a0, a2, a1, a3, b[2*t], b[2*t+1]);
            }
        }

        const int nxt = kt + STAGES - 1;
        if (nxt < NT)
            fill_stage(adj, rowBase, nxt, stage0 + (uint32_t)(nxt & (STAGES - 1)) * STAGE_BYTES, tid);
    }
    asm volatile("cp.async.wait_group 0;" ::: "memory");
    __syncthreads();

    // cross-warp k-half reduction via smem (conflict-free [comp][row] layout)
    if (kh == 1) {
        #pragma unroll
        for (int mi = 0; mi < 2; mi++)
            #pragma unroll
            for (int t = 0; t < 5; t++)
                #pragma unroll
                for (int e = 0; e < 4; e++)
                    ex[(mi * 20 + t * 4 + e) * 128 + wr * 32 + lane] = acc[mi][t][e];
    }
    __syncthreads();
    if (kh == 0) {
        #pragma unroll
        for (int mi = 0; mi < 2; mi++)
            #pragma unroll
            for (int t = 0; t < 5; t++)
                #pragma unroll
                for (int e = 0; e < 4; e++)
                    acc[mi][t][e] += ex[(mi * 20 + t * 4 + e) * 128 + wr * 32 + lane];

        // degree: tile 4, col offset 0 -> lanes lane%4==0 hold col 32 (elems 0 and 2)
        const int srcLane = lane & ~3;
        #pragma unroll
        for (int mi = 0; mi < 2; mi++) {
            float dlo = __shfl_sync(0xffffffffu, acc[mi][4][0], srcLane);
            float dhi = __shfl_sync(0xffffffffu, acc[mi][4][2], srcLane);
            float rd0 = 1.0f / fmaxf(dlo, 1.0f);
            float rd1 = 1.0f / fmaxf(dhi, 1.0f);
            const size_t r0 = rowBase + (size_t)(wr * 32 + mi * 16 + (lane >> 2));
            const size_t r1 = r0 + 8;
            #pragma unroll
            for (int t = 0; t < 4; t++) {
                const int colb = t * 8 + 2 * (lane & 3);
                float2 olo = {acc[mi][t][0] * rd0, acc[mi][t][1] * rd0};
                float2 ohi = {acc[mi][t][2] * rd1, acc[mi][t][3] * rd1};
                *reinterpret_cast<float2*>(&g_agg[r0 * DDIM + colb]) = olo;
                *reinterpret_cast<float2*>(&g_agg[r1 * DDIM + colb]) = ohi;
            }
        }
    }
}

// ==================== Kernel 3: update MLP (proven round-3 shape) ====================
__global__ __launch_bounds__(128) void upd_kernel(
    const float* __restrict__ states, const float* __restrict__ W1,
    const float* __restrict__ b1,     const float* __restrict__ W2,
    const float* __restrict__ b2,     float* __restrict__ out)
{
    __shared__ float sW1[2 * DDIM * HDIM];
    __shared__ float sW2[HDIM * DDIM];
    const int tid = threadIdx.x;
    for (int i = tid; i < 2 * DDIM * HDIM; i += 128) sW1[i] = W1[i];
    for (int i = tid; i < HDIM * DDIM; i += 128)     sW2[i] = W2[i];
    __syncthreads();

    const int row = blockIdx.x * 128 + tid;
    float x[2 * DDIM];
    const float4* sp = reinterpret_cast<const float4*>(states + (size_t)row * DDIM);
    const float4* gp = reinterpret_cast<const float4*>(g_agg  + (size_t)row * DDIM);
    #pragma unroll
    for (int j4 = 0; j4 < DDIM / 4; j4++) {
        float4 v = sp[j4];
        x[4*j4+0] = v.x; x[4*j4+1] = v.y; x[4*j4+2] = v.z; x[4*j4+3] = v.w;
        float4 g = gp[j4];
        x[DDIM+4*j4+0] = g.x; x[DDIM+4*j4+1] = g.y;
        x[DDIM+4*j4+2] = g.z; x[DDIM+4*j4+3] = g.w;
    }
    float m[DDIM];
    #pragma unroll
    for (int d = 0; d < DDIM; d++) m[d] = __ldg(&b2[d]);

    #pragma unroll 2
    for (int hg = 0; hg < HDIM / 4; hg++) {
        float4 hid = __ldg(reinterpret_cast<const float4*>(b1) + hg);
        #pragma unroll
        for (int j = 0; j < 2 * DDIM; j++) {
            float4 w = *reinterpret_cast<const float4*>(&sW1[j * HDIM + 4 * hg]);
            hid.x += x[j] * w.x; hid.y += x[j] * w.y;
            hid.z += x[j] * w.z; hid.w += x[j] * w.w;
        }
        float rr[4] = {fmaxf(hid.x, 0.f), fmaxf(hid.y, 0.f),
                       fmaxf(hid.z, 0.f), fmaxf(hid.w, 0.f)};
        #pragma unroll
        for (int e = 0; e < 4; e++) {
            float r = rr[e];
            #pragma unroll
            for (int d4 = 0; d4 < DDIM / 4; d4++) {
                float4 w = *reinterpret_cast<const float4*>(&sW2[(4*hg+e) * DDIM + 4*d4]);
                m[4*d4+0] += r * w.x; m[4*d4+1] += r * w.y;
                m[4*d4+2] += r * w.z; m[4*d4+3] += r * w.w;
            }
        }
    }
    float4* op = reinterpret_cast<float4*>(out + (size_t)row * DDIM);
    #pragma unroll
    for (int d4 = 0; d4 < DDIM / 4; d4++) {
        float4 o;
        o.x = m[4*d4+0]; o.y = m[4*d4+1]; o.z = m[4*d4+2]; o.w = m[4*d4+3];
        op[d4] = o;
    }
}

// ==================== launch ====================
extern "C" void kernel_launch(void* const* d_in, const int* in_sizes, int n_in,
                              void* d_out, int out_size)
{
    const float* states = (const float*)d_in[0];
    const float* adj    = (const float*)d_in[1];
    const float* mW1    = (const float*)d_in[2];
    const float* mb1    = (const float*)d_in[3];
    const float* mW2    = (const float*)d_in[4];
    const float* mb2    = (const float*)d_in[5];
    const float* uW1    = (const float*)d_in[6];
    const float* ub1    = (const float*)d_in[7];
    const float* uW2    = (const float*)d_in[8];
    const float* ub2    = (const float*)d_in[9];
    float* out = (float*)d_out;

    cudaFuncSetAttribute(agg_kernel, cudaFuncAttributeMaxDynamicSharedMemorySize, SMEM_TOTAL);

    msg_kernel<<<NROWS / 128, 128>>>(states, mW1, mb1, mW2, mb2);
    agg_kernel<<<NROWS / 128, 256, SMEM_TOTAL>>>(adj);
    upd_kernel<<<NROWS / 128, 128>>>(states, uW1, ub1, uW2, ub2, out);
}

// round 7
// speedup vs baseline: 1.5327x; 1.5327x over previous
#include <cuda_runtime.h>
#include <cstdint>

#define NROWS 16384
#define DDIM  32
#define HDIM  128
#define BK    32                 // K floats per stage -> 128B rows
#define BN    48                 // 32 msg cols + degree col(32) + pad to 6 n8-tiles
#define STAGES 8
#define NT    (NROWS / BK)       // 512
#define ABYTES (128 * 128)       // 16384
#define BBYTES (BN * 128)        // 6144
#define STAGE_BYTES (ABYTES + BBYTES)               // 22528
#define SMEM_TOTAL  (1024 + STAGES * STAGE_BYTES)   // 181248

// MLP kernels: dynamic smem sizes
#define EX_STRIDE 33
#define EX_BYTES  (4 * 64 * EX_STRIDE * 4)          // 33792
#define MSG_SMEM  (DDIM * HDIM * 4 + HDIM * DDIM * 4 + EX_BYTES)      // 66560
#define UPD_SMEM  (2 * DDIM * HDIM * 4 + HDIM * DDIM * 4 + EX_BYTES)  // 82944

// device scratch
__device__ float g_msgB[BN * NROWS];   // [col][k]; cols0-31 tf32 msg, col32=1, 33+ junk (unused)
__device__ float g_agg [NROWS * DDIM];

// ---------------- PTX helpers ----------------
__device__ __forceinline__ void cp16(uint32_t dst, const void* src) {
    asm volatile("cp.async.cg.shared.global [%0], [%1], 16;" :: "r"(dst), "l"(src) : "memory");
}
__device__ __forceinline__ float tf32_rna(float x) {
    uint32_t r;
    asm("cvt.rna.tf32.f32 %0, %1;" : "=r"(r) : "f"(x));
    return __uint_as_float(r);
}
__device__ __forceinline__ void ldsm_x4(uint32_t& r0, uint32_t& r1, uint32_t& r2, uint32_t& r3,
                                        uint32_t addr) {
    asm volatile("ldmatrix.sync.aligned.m8n8.x4.shared.b16 {%0,%1,%2,%3}, [%4];"
                 : "=r"(r0), "=r"(r1), "=r"(r2), "=r"(r3) : "r"(addr));
}
__device__ __forceinline__ void mma_tf32(float* c, uint32_t a0, uint32_t a1,
                                         uint32_t a2, uint32_t a3,
                                         uint32_t b0, uint32_t b1) {
    asm volatile(
        "mma.sync.aligned.m16n8k8.row.col.f32.tf32.tf32.f32 "
        "{%0,%1,%2,%3}, {%4,%5,%6,%7}, {%8,%9}, {%0,%1,%2,%3};"
        : "+f"(c[0]), "+f"(c[1]), "+f"(c[2]), "+f"(c[3])
        : "r"(a0), "r"(a1), "r"(a2), "r"(a3), "r"(b0), "r"(b1));
}

// ==================== Kernel 1: message MLP (warp-sliced, q uniform per warp) ==========
// block 256 = 8 warps: warp w -> row-group g=w>>2 (32 rows), hidden slice q=w&3 (32 h)
__global__ __launch_bounds__(256) void msg_kernel(
    const float* __restrict__ states, const float* __restrict__ W1,
    const float* __restrict__ b1,     const float* __restrict__ W2,
    const float* __restrict__ b2)
{
    extern __shared__ float sm[];
    float* sW1 = sm;                                   // [32][128]
    float* sW2 = sm + DDIM * HDIM;                     // [128][32]
    float* ex  = sm + DDIM * HDIM + HDIM * DDIM;       // [4][64][33]

    const int tid = threadIdx.x;
    for (int i = tid; i < DDIM * HDIM; i += 256) sW1[i] = W1[i];
    for (int i = tid; i < HDIM * DDIM; i += 256) sW2[i] = W2[i];
    __syncthreads();

    const int wid  = tid >> 5, lane = tid & 31;
    const int g = wid >> 2, q = wid & 3;               // q uniform in warp -> broadcast LDS
    const int rowL = g * 32 + lane;
    const int row  = blockIdx.x * 64 + rowL;

    float s[DDIM];
    const float4* sp = reinterpret_cast<const float4*>(states + (size_t)row * DDIM);
    #pragma unroll
    for (int j4 = 0; j4 < 8; j4++) {
        float4 v = sp[j4];
        s[4*j4+0] = v.x; s[4*j4+1] = v.y; s[4*j4+2] = v.z; s[4*j4+3] = v.w;
    }
    float hid[32];
    #pragma unroll
    for (int h4 = 0; h4 < 8; h4++) {
        float4 b = __ldg(reinterpret_cast<const float4*>(b1 + q * 32) + h4);
        hid[4*h4+0] = b.x; hid[4*h4+1] = b.y; hid[4*h4+2] = b.z; hid[4*h4+3] = b.w;
    }
    #pragma unroll
    for (int j = 0; j < DDIM; j++) {
        const float sj = s[j];
        #pragma unroll
        for (int h4 = 0; h4 < 8; h4++) {
            float4 w = *reinterpret_cast<const float4*>(&sW1[j * HDIM + q * 32 + 4 * h4]);
            hid[4*h4+0] += sj * w.x; hid[4*h4+1] += sj * w.y;
            hid[4*h4+2] += sj * w.z; hid[4*h4+3] += sj * w.w;
        }
    }
    float m[DDIM];
    #pragma unroll
    for (int d = 0; d < DDIM; d++) m[d] = 0.f;
    #pragma unroll
    for (int h = 0; h < 32; h++) {
        float r = fmaxf(hid[h], 0.f);
        #pragma unroll
        for (int d4 = 0; d4 < 8; d4++) {
            float4 w = *reinterpret_cast<const float4*>(&sW2[(q * 32 + h) * DDIM + 4 * d4]);
            m[4*d4+0] += r * w.x; m[4*d4+1] += r * w.y;
            m[4*d4+2] += r * w.z; m[4*d4+3] += r * w.w;
        }
    }
    // exchange: ex[q][rowL][d], stride 33 -> conflict-free both phases
    #pragma unroll
    for (int d = 0; d < DDIM; d++)
        ex[(q * 64 + rowL) * EX_STRIDE + d] = m[d];
    __syncthreads();

    // phase 2: thread -> (row2 = tid>>2, dgroup = (tid&3)*8)
    const int row2 = tid >> 2;
    const int dg   = (tid & 3) * 8;
    const int rowG = blockIdx.x * 64 + row2;
    #pragma unroll
    for (int e = 0; e < 8; e++) {
        const int d = dg + e;
        float v = __ldg(&b2[d]);
        #pragma unroll
        for (int qq = 0; qq < 4; qq++)
            v += ex[(qq * 64 + row2) * EX_STRIDE + d];
        g_msgB[(size_t)d * NROWS + rowG] = tf32_rna(v);
    }
    if (dg == 0)
        g_msgB[(size_t)32 * NROWS + rowG] = 1.0f;      // degree ones-column
}

// ==================== Kernel 2: tf32 aggregation (EXACT round-3 config) ====================
__device__ __forceinline__ void fill_stage(const float* __restrict__ adj, size_t rowBase,
                                           int tile, uint32_t stage, int tid)
{
    const float* aSrc = adj + rowBase * NROWS + (size_t)tile * BK;
    #pragma unroll
    for (int i = 0; i < 4; i++) {                     // A: 1024 16B chunks
        int c = tid + 256 * i;
        int r = c >> 3, k4 = c & 7;
        uint32_t dst = stage + ((r * 8 + (k4 ^ (r & 7))) << 4);
        cp16(dst, aSrc + (size_t)r * NROWS + (k4 << 2));
    }
    {                                                 // B: 384 chunks
        int c = tid;
        int r = c >> 3, k4 = c & 7;
        uint32_t dst = stage + ABYTES + ((r * 8 + (k4 ^ (r & 7))) << 4);
        cp16(dst, g_msgB + (size_t)r * NROWS + (size_t)tile * BK + (k4 << 2));
        c = tid + 256;
        if (c < BN * 8) {
            r = c >> 3; k4 = c & 7;
            dst = stage + ABYTES + ((r * 8 + (k4 ^ (r & 7))) << 4);
            cp16(dst, g_msgB + (size_t)r * NROWS + (size_t)tile * BK + (k4 << 2));
        }
    }
    asm volatile("cp.async.commit_group;" ::: "memory");
}

__global__ __launch_bounds__(256, 1) void agg_kernel(const float* __restrict__ adj)
{
    extern __shared__ char smem[];
    uint32_t sraw = (uint32_t)__cvta_generic_to_shared(smem);
    const uint32_t stage0 = (sraw + 1023u) & ~1023u;

    const int tid  = threadIdx.x;
    const int wid  = tid >> 5;
    const int lane = tid & 31;
    const size_t rowBase = (size_t)blockIdx.x * 128;

    const int jm = lane >> 3;        // matrix index 0..3
    const int qm = lane & 7;         // row within matrix
    const int arow = wid * 16 + (jm >> 1) * 8 + qm;    // A row for this lane

    float acc[5][4];
    #pragma unroll
    for (int nt = 0; nt < 5; nt++)
        #pragma unroll
        for (int e = 0; e < 4; e++) acc[nt][e] = 0.f;

    for (int t = 0; t < STAGES - 1; t++)
        fill_stage(adj, rowBase, t, stage0 + t * STAGE_BYTES, tid);

    for (int kt = 0; kt < NT; kt++) {
        asm volatile("cp.async.wait_group %0;" :: "n"(STAGES - 2) : "memory");
        __syncthreads();

        const uint32_t sA = stage0 + (uint32_t)(kt & (STAGES - 1)) * STAGE_BYTES;
        const uint32_t sB = sA + ABYTES;

        #pragma unroll
        for (int s = 0; s < 4; s++) {
            const int ch = 2 * s + (jm & 1);
            uint32_t a0, a1, a2, a3;
            ldsm_x4(a0, a1, a2, a3, sA + ((arow * 8 + (ch ^ (arow & 7))) << 4));
            uint32_t b[12];
            #pragma unroll
            for (int g = 0; g < 3; g++) {
                const int nrow = g * 16 + (jm >> 1) * 8 + qm;
                ldsm_x4(b[4*g+0], b[4*g+1], b[4*g+2], b[4*g+3],
                        sB + ((nrow * 8 + (ch ^ (nrow & 7))) << 4));
            }
            #pragma unroll
            for (int nt = 0; nt < 5; nt++) {
                const uint32_t b0 = b[(nt >> 1) * 4 + (nt & 1) * 2];
                const uint32_t b1 = b[(nt >> 1) * 4 + (nt & 1) * 2 + 1];
                mma_tf32(acc[nt], a0, a2, a1, a3, b0, b1);
            }
        }

        const int nxt = kt + STAGES - 1;
        if (nxt < NT)
            fill_stage(adj, rowBase, nxt, stage0 + (uint32_t)(nxt & (STAGES - 1)) * STAGE_BYTES, tid);
    }

    // degree = column 32 = n-tile 4, col offset 0 (held by lanes with lane%4==0)
    const int srcLane = lane & ~3;
    float dlo = __shfl_sync(0xffffffffu, acc[4][0], srcLane);
    float dhi = __shfl_sync(0xffffffffu, acc[4][2], srcLane);
    float rdlo = 1.0f / fmaxf(dlo, 1.0f);
    float rdhi = 1.0f / fmaxf(dhi, 1.0f);

    const size_t rlo = rowBase + (size_t)(wid * 16 + (lane >> 2));
    const size_t rhi = rlo + 8;
    const int coff = 2 * (lane & 3);
    #pragma unroll
    for (int nt = 0; nt < 4; nt++) {
        float2 olo = {acc[nt][0] * rdlo, acc[nt][1] * rdlo};
        float2 ohi = {acc[nt][2] * rdhi, acc[nt][3] * rdhi};
        *reinterpret_cast<float2*>(&g_agg[rlo * DDIM + 8 * nt + coff]) = olo;
        *reinterpret_cast<float2*>(&g_agg[rhi * DDIM + 8 * nt + coff]) = ohi;
    }
}

// ==================== Kernel 3: update MLP (warp-sliced) ====================
__global__ __launch_bounds__(256) void upd_kernel(
    const float* __restrict__ states, const float* __restrict__ W1,
    const float* __restrict__ b1,     const float* __restrict__ W2,
    const float* __restrict__ b2,     float* __restrict__ out)
{
    extern __shared__ float sm[];
    float* sW1 = sm;                                       // [64][128]
    float* sW2 = sm + 2 * DDIM * HDIM;                     // [128][32]
    float* ex  = sm + 2 * DDIM * HDIM + HDIM * DDIM;       // [4][64][33]

    const int tid = threadIdx.x;
    for (int i = tid; i < 2 * DDIM * HDIM; i += 256) sW1[i] = W1[i];
    for (int i = tid; i < HDIM * DDIM; i += 256)     sW2[i] = W2[i];
    __syncthreads();

    const int wid  = tid >> 5, lane = tid & 31;
    const int g = wid >> 2, q = wid & 3;
    const int rowL = g * 32 + lane;
    const int row  = blockIdx.x * 64 + rowL;

    float x[2 * DDIM];
    const float4* sp = reinterpret_cast<const float4*>(states + (size_t)row * DDIM);
    const float4* gp = reinterpret_cast<const float4*>(g_agg  + (size_t)row * DDIM);
    #pragma unroll
    for (int j4 = 0; j4 < 8; j4++) {
        float4 v = sp[j4];
        x[4*j4+0] = v.x; x[4*j4+1] = v.y; x[4*j4+2] = v.z; x[4*j4+3] = v.w;
        float4 gg = gp[j4];
        x[DDIM+4*j4+0] = gg.x; x[DDIM+4*j4+1] = gg.y;
        x[DDIM+4*j4+2] = gg.z; x[DDIM+4*j4+3] = gg.w;
    }
    float hid[32];
    #pragma unroll
    for (int h4 = 0; h4 < 8; h4++) {
        float4 b = __ldg(reinterpret_cast<const float4*>(b1 + q * 32) + h4);
        hid[4*h4+0] = b.x; hid[4*h4+1] = b.y; hid[4*h4+2] = b.z; hid[4*h4+3] = b.w;
    }
    #pragma unroll
    for (int j = 0; j < 2 * DDIM; j++) {
        const float xj = x[j];
        #pragma unroll
        for (int h4 = 0; h4 < 8; h4++) {
            float4 w = *reinterpret_cast<const float4*>(&sW1[j * HDIM + q * 32 + 4 * h4]);
            hid[4*h4+0] += xj * w.x; hid[4*h4+1] += xj * w.y;
            hid[4*h4+2] += xj * w.z; hid[4*h4+3] += xj * w.w;
        }
    }
    float m[DDIM];
    #pragma unroll
    for (int d = 0; d < DDIM; d++) m[d] = 0.f;
    #pragma unroll
    for (int h = 0; h < 32; h++) {
        float r = fmaxf(hid[h], 0.f);
        #pragma unroll
        for (int d4 = 0; d4 < 8; d4++) {
            float4 w = *reinterpret_cast<const float4*>(&sW2[(q * 32 + h) * DDIM + 4 * d4]);
            m[4*d4+0] += r * w.x; m[4*d4+1] += r * w.y;
            m[4*d4+2] += r * w.z; m[4*d4+3] += r * w.w;
        }
    }
    #pragma unroll
    for (int d = 0; d < DDIM; d++)
        ex[(q * 64 + rowL) * EX_STRIDE + d] = m[d];
    __syncthreads();

    const int row2 = tid >> 2;
    const int dg   = (tid & 3) * 8;
    const size_t rowG = (size_t)blockIdx.x * 64 + row2;
    float o[8];
    #pragma unroll
    for (int e = 0; e < 8; e++) {
        const int d = dg + e;
        float v = __ldg(&b2[d]);
        #pragma unroll
        for (int qq = 0; qq < 4; qq++)
            v += ex[(qq * 64 + row2) * EX_STRIDE + d];
        o[e] = v;
    }
    float4* op = reinterpret_cast<float4*>(out + rowG * DDIM + dg);
    op[0] = make_float4(o[0], o[1], o[2], o[3]);
    op[1] = make_float4(o[4], o[5], o[6], o[7]);
}

// ==================== launch ====================
extern "C" void kernel_launch(void* const* d_in, const int* in_sizes, int n_in,
                              void* d_out, int out_size)
{
    const float* states = (const float*)d_in[0];
    const float* adj    = (const float*)d_in[1];
    const float* mW1    = (const float*)d_in[2];
    const float* mb1    = (const float*)d_in[3];
    const float* mW2    = (const float*)d_in[4];
    const float* mb2    = (const float*)d_in[5];
    const float* uW1    = (const float*)d_in[6];
    const float* ub1    = (const float*)d_in[7];
    const float* uW2    = (const float*)d_in[8];
    const float* ub2    = (const float*)d_in[9];
    float* out = (float*)d_out;

    cudaFuncSetAttribute(agg_kernel, cudaFuncAttributeMaxDynamicSharedMemorySize, SMEM_TOTAL);
    cudaFuncSetAttribute(msg_kernel, cudaFuncAttributeMaxDynamicSharedMemorySize, MSG_SMEM);
    cudaFuncSetAttribute(upd_kernel, cudaFuncAttributeMaxDynamicSharedMemorySize, UPD_SMEM);

    msg_kernel<<<NROWS / 64, 256, MSG_SMEM>>>(states, mW1, mb1, mW2, mb2);
    agg_kernel<<<NROWS / 128, 256, SMEM_TOTAL>>>(adj);
    upd_kernel<<<NROWS / 64, 256, UPD_SMEM>>>(states, uW1, ub1, uW2, ub2, out);
}

// round 8
// speedup vs baseline: 1.6248x; 1.0601x over previous
#include <cuda_runtime.h>
#include <cstdint>

#define NROWS 16384
#define DDIM  32
#define HDIM  128
#define BK    32                 // K floats per stage -> 128B rows
#define BN    40                 // 32 msg cols + degree(col32) + 7 zero pad
#define STAGES 8
#define NT    (NROWS / BK)       // 512
#define ABYTES (128 * 128)       // 16384
#define BBYTES (BN * 128)        // 5120
#define STAGE_BYTES (ABYTES + BBYTES)               // 21504
#define SMEM_TOTAL  (1024 + STAGES * STAGE_BYTES)   // 173056

// update MLP smem
#define EX_STRIDE 33
#define EX_BYTES  (4 * 64 * EX_STRIDE * 4)
#define UPD_SMEM  (2 * DDIM * HDIM * 4 + HDIM * DDIM * 4 + EX_BYTES)  // 82944

// device scratch
__device__ float g_msgB[BN * NROWS];   // [col][k]; cols0-31 tf32 msg, col32=1, 33-39=0
__device__ float g_agg [NROWS * DDIM];

// ---------------- PTX helpers ----------------
__device__ __forceinline__ void cp16(uint32_t dst, const void* src) {
    asm volatile("cp.async.cg.shared.global [%0], [%1], 16;" :: "r"(dst), "l"(src) : "memory");
}
__device__ __forceinline__ float tf32_rna(float x) {
    uint32_t r;
    asm("cvt.rna.tf32.f32 %0, %1;" : "=r"(r) : "f"(x));
    return __uint_as_float(r);
}
__device__ __forceinline__ void ldsm_x4(uint32_t& r0, uint32_t& r1, uint32_t& r2, uint32_t& r3,
                                        uint32_t addr) {
    asm volatile("ldmatrix.sync.aligned.m8n8.x4.shared.b16 {%0,%1,%2,%3}, [%4];"
                 : "=r"(r0), "=r"(r1), "=r"(r2), "=r"(r3) : "r"(addr));
}
__device__ __forceinline__ void ldsm_x2(uint32_t& r0, uint32_t& r1, uint32_t addr) {
    asm volatile("ldmatrix.sync.aligned.m8n8.x2.shared.b16 {%0,%1}, [%2];"
                 : "=r"(r0), "=r"(r1) : "r"(addr));
}
__device__ __forceinline__ void mma_tf32(float* c, uint32_t a0, uint32_t a1,
                                         uint32_t a2, uint32_t a3,
                                         uint32_t b0, uint32_t b1) {
    asm volatile(
        "mma.sync.aligned.m16n8k8.row.col.f32.tf32.tf32.f32 "
        "{%0,%1,%2,%3}, {%4,%5,%6,%7}, {%8,%9}, {%0,%1,%2,%3};"
        : "+f"(c[0]), "+f"(c[1]), "+f"(c[2]), "+f"(c[3])
        : "r"(a0), "r"(a1), "r"(a2), "r"(a3), "r"(b0), "r"(b1));
}

// ==================== Kernel 1: message MLP (round-3 exact) ====================
__global__ __launch_bounds__(128) void msg_kernel(
    const float* __restrict__ states, const float* __restrict__ W1,
    const float* __restrict__ b1,     const float* __restrict__ W2,
    const float* __restrict__ b2)
{
    __shared__ float sW1[DDIM * HDIM];
    __shared__ float sW2[HDIM * DDIM];
    const int tid = threadIdx.x;
    for (int i = tid; i < DDIM * HDIM; i += 128) sW1[i] = W1[i];
    for (int i = tid; i < HDIM * DDIM; i += 128) sW2[i] = W2[i];
    __syncthreads();

    const int row = blockIdx.x * 128 + tid;
    float s[DDIM];
    const float4* sp = reinterpret_cast<const float4*>(states + (size_t)row * DDIM);
    #pragma unroll
    for (int j4 = 0; j4 < DDIM / 4; j4++) {
        float4 v = sp[j4];
        s[4*j4+0] = v.x; s[4*j4+1] = v.y; s[4*j4+2] = v.z; s[4*j4+3] = v.w;
    }
    float m[DDIM];
    #pragma unroll
    for (int d = 0; d < DDIM; d++) m[d] = __ldg(&b2[d]);

    #pragma unroll 2
    for (int hg = 0; hg < HDIM / 4; hg++) {
        float4 hid = __ldg(reinterpret_cast<const float4*>(b1) + hg);
        #pragma unroll
        for (int j = 0; j < DDIM; j++) {
            float4 w = *reinterpret_cast<const float4*>(&sW1[j * HDIM + 4 * hg]);
            hid.x += s[j] * w.x; hid.y += s[j] * w.y;
            hid.z += s[j] * w.z; hid.w += s[j] * w.w;
        }
        float rr[4] = {fmaxf(hid.x, 0.f), fmaxf(hid.y, 0.f),
                       fmaxf(hid.z, 0.f), fmaxf(hid.w, 0.f)};
        #pragma unroll
        for (int e = 0; e < 4; e++) {
            float r = rr[e];
            #pragma unroll
            for (int d4 = 0; d4 < DDIM / 4; d4++) {
                float4 w = *reinterpret_cast<const float4*>(&sW2[(4*hg+e) * DDIM + 4*d4]);
                m[4*d4+0] += r * w.x; m[4*d4+1] += r * w.y;
                m[4*d4+2] += r * w.z; m[4*d4+3] += r * w.w;
            }
        }
    }
    #pragma unroll
    for (int d = 0; d < DDIM; d++)
        g_msgB[(size_t)d * NROWS + row] = tf32_rna(m[d]);
    g_msgB[(size_t)32 * NROWS + row] = 1.0f;          // degree column
    #pragma unroll
    for (int d = 33; d < BN; d++)
        g_msgB[(size_t)d * NROWS + row] = 0.0f;       // pad
}

// ==================== Kernel 2: tf32 aggregation (round-3 structure, BN=40) ==========
__device__ __forceinline__ void fill_stage(const float* __restrict__ adj, size_t rowBase,
                                           int tile, uint32_t stage, int tid)
{
    const float* aSrc = adj + rowBase * NROWS + (size_t)tile * BK;
    #pragma unroll
    for (int i = 0; i < 4; i++) {                     // A: 1024 16B chunks
        int c = tid + 256 * i;
        int r = c >> 3, k4 = c & 7;
        uint32_t dst = stage + ((r * 8 + (k4 ^ (r & 7))) << 4);
        cp16(dst, aSrc + (size_t)r * NROWS + (k4 << 2));
    }
    {                                                 // B: 320 chunks (40 rows)
        int r = tid >> 3, k4 = tid & 7;
        uint32_t dst = stage + ABYTES + ((r * 8 + (k4 ^ (r & 7))) << 4);
        cp16(dst, g_msgB + (size_t)r * NROWS + (size_t)tile * BK + (k4 << 2));
        if (tid < 64) {
            int c = tid + 256;
            r = c >> 3; k4 = c & 7;
            dst = stage + ABYTES + ((r * 8 + (k4 ^ (r & 7))) << 4);
            cp16(dst, g_msgB + (size_t)r * NROWS + (size_t)tile * BK + (k4 << 2));
        }
    }
    asm volatile("cp.async.commit_group;" ::: "memory");
}

__global__ __launch_bounds__(256, 1) void agg_kernel(const float* __restrict__ adj)
{
    extern __shared__ char smem[];
    uint32_t sraw = (uint32_t)__cvta_generic_to_shared(smem);
    const uint32_t stage0 = (sraw + 1023u) & ~1023u;

    const int tid  = threadIdx.x;
    const int wid  = tid >> 5;
    const int lane = tid & 31;
    const size_t rowBase = (size_t)blockIdx.x * 128;

    const int jm = lane >> 3;        // matrix index 0..3
    const int qm = lane & 7;         // row within matrix
    const int hb = jm & 1;           // x2 half select
    const int arow = wid * 16 + (jm >> 1) * 8 + qm;    // A row for this lane

    float acc[5][4];
    #pragma unroll
    for (int nt = 0; nt < 5; nt++)
        #pragma unroll
        for (int e = 0; e < 4; e++) acc[nt][e] = 0.f;

    for (int t = 0; t < STAGES - 1; t++)
        fill_stage(adj, rowBase, t, stage0 + t * STAGE_BYTES, tid);

    for (int kt = 0; kt < NT; kt++) {
        asm volatile("cp.async.wait_group %0;" :: "n"(STAGES - 2) : "memory");
        __syncthreads();

        const uint32_t sA = stage0 + (uint32_t)(kt & (STAGES - 1)) * STAGE_BYTES;
        const uint32_t sB = sA + ABYTES;

        #pragma unroll
        for (int s = 0; s < 4; s++) {
            const int ch  = 2 * s + (jm & 1);
            const int chx = 2 * s + hb;
            uint32_t a0, a1, a2, a3;
            ldsm_x4(a0, a1, a2, a3, sA + ((arow * 8 + (ch ^ (arow & 7))) << 4));
            uint32_t b[10];
            {
                const int nr0 = (jm >> 1) * 8 + qm;            // rows 0-15 -> tiles 0,1
                ldsm_x4(b[0], b[1], b[2], b[3],
                        sB + ((nr0 * 8 + (ch ^ (nr0 & 7))) << 4));
                const int nr1 = 16 + (jm >> 1) * 8 + qm;        // rows 16-31 -> tiles 2,3
                ldsm_x4(b[4], b[5], b[6], b[7],
                        sB + ((nr1 * 8 + (ch ^ (nr1 & 7))) << 4));
                const int nr2 = 32 + qm;                        // rows 32-39 -> tile 4
                ldsm_x2(b[8], b[9], sB + ((nr2 * 8 + (chx ^ (nr2 & 7))) << 4));
            }
            #pragma unroll
            for (int nt = 0; nt < 5; nt++)
                mma_tf32(acc[nt], a0, a2, a1, a3, b[2*nt], b[2*nt+1]);
        }

        const int nxt = kt + STAGES - 1;
        if (nxt < NT)
            fill_stage(adj, rowBase, nxt, stage0 + (uint32_t)(nxt & (STAGES - 1)) * STAGE_BYTES, tid);
    }

    // degree = col 32 = tile 4 col offset 0 (lanes lane%4==0, elems 0 and 2)
    const int srcLane = lane & ~3;
    float dlo = __shfl_sync(0xffffffffu, acc[4][0], srcLane);
    float dhi = __shfl_sync(0xffffffffu, acc[4][2], srcLane);
    float rdlo = 1.0f / fmaxf(dlo, 1.0f);
    float rdhi = 1.0f / fmaxf(dhi, 1.0f);

    const size_t rlo = rowBase + (size_t)(wid * 16 + (lane >> 2));
    const size_t rhi = rlo + 8;
    const int coff = 2 * (lane & 3);
    #pragma unroll
    for (int nt = 0; nt < 4; nt++) {
        float2 olo = {acc[nt][0] * rdlo, acc[nt][1] * rdlo};
        float2 ohi = {acc[nt][2] * rdhi, acc[nt][3] * rdhi};
        *reinterpret_cast<float2*>(&g_agg[rlo * DDIM + 8 * nt + coff]) = olo;
        *reinterpret_cast<float2*>(&g_agg[rhi * DDIM + 8 * nt + coff]) = ohi;
    }
}

// ==================== Kernel 3: update MLP (round-7 warp-sliced) ====================
__global__ __launch_bounds__(256) void upd_kernel(
    const float* __restrict__ states, const float* __restrict__ W1,
    const float* __restrict__ b1,     const float* __restrict__ W2,
    const float* __restrict__ b2,     float* __restrict__ out)
{
    extern __shared__ float sm[];
    float* sW1 = sm;                                       // [64][128]
    float* sW2 = sm + 2 * DDIM * HDIM;                     // [128][32]
    float* ex  = sm + 2 * DDIM * HDIM + HDIM * DDIM;       // [4][64][33]

    const int tid = threadIdx.x;
    for (int i = tid; i < 2 * DDIM * HDIM; i += 256) sW1[i] = W1[i];
    for (int i = tid; i < HDIM * DDIM; i += 256)     sW2[i] = W2[i];
    __syncthreads();

    const int wid  = tid >> 5, lane = tid & 31;
    const int g = wid >> 2, q = wid & 3;
    const int rowL = g * 32 + lane;
    const int row  = blockIdx.x * 64 + rowL;

    float x[2 * DDIM];
    const float4* sp = reinterpret_cast<const float4*>(states + (size_t)row * DDIM);
    const float4* gp = reinterpret_cast<const float4*>(g_agg  + (size_t)row * DDIM);
    #pragma unroll
    for (int j4 = 0; j4 < 8; j4++) {
        float4 v = sp[j4];
        x[4*j4+0] = v.x; x[4*j4+1] = v.y; x[4*j4+2] = v.z; x[4*j4+3] = v.w;
        float4 gg = gp[j4];
        x[DDIM+4*j4+0] = gg.x; x[DDIM+4*j4+1] = gg.y;
        x[DDIM+4*j4+2] = gg.z; x[DDIM+4*j4+3] = gg.w;
    }
    float hid[32];
    #pragma unroll
    for (int h4 = 0; h4 < 8; h4++) {
        float4 b = __ldg(reinterpret_cast<const float4*>(b1 + q * 32) + h4);
        hid[4*h4+0] = b.x; hid[4*h4+1] = b.y; hid[4*h4+2] = b.z; hid[4*h4+3] = b.w;
    }
    #pragma unroll
    for (int j = 0; j < 2 * DDIM; j++) {
        const float xj = x[j];
        #pragma unroll
        for (int h4 = 0; h4 < 8; h4++) {
            float4 w = *reinterpret_cast<const float4*>(&sW1[j * HDIM + q * 32 + 4 * h4]);
            hid[4*h4+0] += xj * w.x; hid[4*h4+1] += xj * w.y;
            hid[4*h4+2] += xj * w.z; hid[4*h4+3] += xj * w.w;
        }
    }
    float m[DDIM];
    #pragma unroll
    for (int d = 0; d < DDIM; d++) m[d] = 0.f;
    #pragma unroll
    for (int h = 0; h < 32; h++) {
        float r = fmaxf(hid[h], 0.f);
        #pragma unroll
        for (int d4 = 0; d4 < 8; d4++) {
            float4 w = *reinterpret_cast<const float4*>(&sW2[(q * 32 + h) * DDIM + 4 * d4]);
            m[4*d4+0] += r * w.x; m[4*d4+1] += r * w.y;
            m[4*d4+2] += r * w.z; m[4*d4+3] += r * w.w;
        }
    }
    #pragma unroll
    for (int d = 0; d < DDIM; d++)
        ex[(q * 64 + rowL) * EX_STRIDE + d] = m[d];
    __syncthreads();

    const int row2 = tid >> 2;
    const int dg   = (tid & 3) * 8;
    const size_t rowG = (size_t)blockIdx.x * 64 + row2;
    float o[8];
    #pragma unroll
    for (int e = 0; e < 8; e++) {
        const int d = dg + e;
        float v = __ldg(&b2[d]);
        #pragma unroll
        for (int qq = 0; qq < 4; qq++)
            v += ex[(qq * 64 + row2) * EX_STRIDE + d];
        o[e] = v;
    }
    float4* op = reinterpret_cast<float4*>(out + rowG * DDIM + dg);
    op[0] = make_float4(o[0], o[1], o[2], o[3]);
    op[1] = make_float4(o[4], o[5], o[6], o[7]);
}

// ==================== launch ====================
extern "C" void kernel_launch(void* const* d_in, const int* in_sizes, int n_in,
                              void* d_out, int out_size)
{
    const float* states = (const float*)d_in[0];
    const float* adj    = (const float*)d_in[1];
    const float* mW1    = (const float*)d_in[2];
    const float* mb1    = (const float*)d_in[3];
    const float* mW2    = (const float*)d_in[4];
    const float* mb2    = (const float*)d_in[5];
    const float* uW1    = (const float*)d_in[6];
    const float* ub1    = (const float*)d_in[7];
    const float* uW2    = (const float*)d_in[8];
    const float* ub2    = (const float*)d_in[9];
    float* out = (float*)d_out;

    cudaFuncSetAttribute(agg_kernel, cudaFuncAttributeMaxDynamicSharedMemorySize, SMEM_TOTAL);
    cudaFuncSetAttribute(upd_kernel, cudaFuncAttributeMaxDynamicSharedMemorySize, UPD_SMEM);

    msg_kernel<<<NROWS / 128, 128>>>(states, mW1, mb1, mW2, mb2);
    agg_kernel<<<NROWS / 128, 256, SMEM_TOTAL>>>(adj);
    upd_kernel<<<NROWS / 64, 256, UPD_SMEM>>>(states, uW1, ub1, uW2, ub2, out);
}

// round 9
// speedup vs baseline: 1.6293x; 1.0028x over previous
#include <cuda_runtime.h>
#include <cstdint>

#define NROWS 16384
#define DDIM  32
#define HDIM  128
#define BK    32                 // K floats per stage -> 128B rows
#define BN    40                 // smem B rows: 33 live (32 msg + degree), 7 garbage-pad
#define BLIVE 33                 // rows actually streamed
#define STAGES 8
#define NT    (NROWS / BK)       // 512
#define ABYTES (128 * 128)       // 16384
#define BBYTES (BN * 128)        // 5120
#define STAGE_BYTES (ABYTES + BBYTES)               // 21504
#define SMEM_TOTAL  (1024 + STAGES * STAGE_BYTES)   // 173056

// update MLP smem
#define EX_STRIDE 33
#define EX_BYTES  (4 * 64 * EX_STRIDE * 4)
#define UPD_SMEM  (2 * DDIM * HDIM * 4 + HDIM * DDIM * 4 + EX_BYTES)  // 82944

// device scratch
__device__ float g_msgB[BN * NROWS];   // [col][k]; cols0-31 tf32 msg, col32=1 (33+ unused)
__device__ float g_agg [NROWS * DDIM];

// ---------------- PTX helpers ----------------
__device__ __forceinline__ void cp16(uint32_t dst, const void* src) {
    asm volatile("cp.async.cg.shared.global [%0], [%1], 16;" :: "r"(dst), "l"(src) : "memory");
}
__device__ __forceinline__ float tf32_rna(float x) {
    uint32_t r;
    asm("cvt.rna.tf32.f32 %0, %1;" : "=r"(r) : "f"(x));
    return __uint_as_float(r);
}
__device__ __forceinline__ void ldsm_x4(uint32_t& r0, uint32_t& r1, uint32_t& r2, uint32_t& r3,
                                        uint32_t addr) {
    asm volatile("ldmatrix.sync.aligned.m8n8.x4.shared.b16 {%0,%1,%2,%3}, [%4];"
                 : "=r"(r0), "=r"(r1), "=r"(r2), "=r"(r3) : "r"(addr));
}
__device__ __forceinline__ void ldsm_x2(uint32_t& r0, uint32_t& r1, uint32_t addr) {
    asm volatile("ldmatrix.sync.aligned.m8n8.x2.shared.b16 {%0,%1}, [%2];"
                 : "=r"(r0), "=r"(r1) : "r"(addr));
}
__device__ __forceinline__ void mma_tf32(float* c, uint32_t a0, uint32_t a1,
                                         uint32_t a2, uint32_t a3,
                                         uint32_t b0, uint32_t b1) {
    asm volatile(
        "mma.sync.aligned.m16n8k8.row.col.f32.tf32.tf32.f32 "
        "{%0,%1,%2,%3}, {%4,%5,%6,%7}, {%8,%9}, {%0,%1,%2,%3};"
        : "+f"(c[0]), "+f"(c[1]), "+f"(c[2]), "+f"(c[3])
        : "r"(a0), "r"(a1), "r"(a2), "r"(a3), "r"(b0), "r"(b1));
}

// ==================== Kernel 1: message MLP (round-3 shape, deeper unroll) ==========
__global__ __launch_bounds__(128) void msg_kernel(
    const float* __restrict__ states, const float* __restrict__ W1,
    const float* __restrict__ b1,     const float* __restrict__ W2,
    const float* __restrict__ b2)
{
    __shared__ float sW1[DDIM * HDIM];
    __shared__ float sW2[HDIM * DDIM];
    const int tid = threadIdx.x;
    for (int i = tid; i < DDIM * HDIM; i += 128) sW1[i] = W1[i];
    for (int i = tid; i < HDIM * DDIM; i += 128) sW2[i] = W2[i];
    __syncthreads();

    const int row = blockIdx.x * 128 + tid;
    float s[DDIM];
    const float4* sp = reinterpret_cast<const float4*>(states + (size_t)row * DDIM);
    #pragma unroll
    for (int j4 = 0; j4 < DDIM / 4; j4++) {
        float4 v = sp[j4];
        s[4*j4+0] = v.x; s[4*j4+1] = v.y; s[4*j4+2] = v.z; s[4*j4+3] = v.w;
    }
    float m[DDIM];
    #pragma unroll
    for (int d = 0; d < DDIM; d++) m[d] = __ldg(&b2[d]);

    #pragma unroll 4
    for (int hg = 0; hg < HDIM / 4; hg++) {
        float4 hid = __ldg(reinterpret_cast<const float4*>(b1) + hg);
        #pragma unroll
        for (int j = 0; j < DDIM; j++) {
            float4 w = *reinterpret_cast<const float4*>(&sW1[j * HDIM + 4 * hg]);
            hid.x += s[j] * w.x; hid.y += s[j] * w.y;
            hid.z += s[j] * w.z; hid.w += s[j] * w.w;
        }
        float rr[4] = {fmaxf(hid.x, 0.f), fmaxf(hid.y, 0.f),
                       fmaxf(hid.z, 0.f), fmaxf(hid.w, 0.f)};
        #pragma unroll
        for (int e = 0; e < 4; e++) {
            float r = rr[e];
            #pragma unroll
            for (int d4 = 0; d4 < DDIM / 4; d4++) {
                float4 w = *reinterpret_cast<const float4*>(&sW2[(4*hg+e) * DDIM + 4*d4]);
                m[4*d4+0] += r * w.x; m[4*d4+1] += r * w.y;
                m[4*d4+2] += r * w.z; m[4*d4+3] += r * w.w;
            }
        }
    }
    #pragma unroll
    for (int d = 0; d < DDIM; d++)
        g_msgB[(size_t)d * NROWS + row] = tf32_rna(m[d]);
    g_msgB[(size_t)32 * NROWS + row] = 1.0f;          // degree column
}

// ==================== Kernel 2: tf32 aggregation (round-8 + fill hoist) ==========
__device__ __forceinline__ void fill_stage(const float* __restrict__ adj, size_t rowBase,
                                           int tile, uint32_t stage, int tid)
{
    const float* aSrc = adj + rowBase * NROWS + (size_t)tile * BK;
    #pragma unroll
    for (int i = 0; i < 4; i++) {                     // A: 1024 16B chunks
        int c = tid + 256 * i;
        int r = c >> 3, k4 = c & 7;
        uint32_t dst = stage + ((r * 8 + (k4 ^ (r & 7))) << 4);
        cp16(dst, aSrc + (size_t)r * NROWS + (k4 << 2));
    }
    {                                                 // B: 264 chunks (33 live rows)
        int r = tid >> 3, k4 = tid & 7;
        uint32_t dst = stage + ABYTES + ((r * 8 + (k4 ^ (r & 7))) << 4);
        cp16(dst, g_msgB + (size_t)r * NROWS + (size_t)tile * BK + (k4 << 2));
        if (tid < 8) {
            int c = tid + 256;
            r = c >> 3; k4 = c & 7;
            dst = stage + ABYTES + ((r * 8 + (k4 ^ (r & 7))) << 4);
            cp16(dst, g_msgB + (size_t)r * NROWS + (size_t)tile * BK + (k4 << 2));
        }
    }
    asm volatile("cp.async.commit_group;" ::: "memory");
}

__global__ __launch_bounds__(256, 1) void agg_kernel(const float* __restrict__ adj)
{
    extern __shared__ char smem[];
    uint32_t sraw = (uint32_t)__cvta_generic_to_shared(smem);
    const uint32_t stage0 = (sraw + 1023u) & ~1023u;

    const int tid  = threadIdx.x;
    const int wid  = tid >> 5;
    const int lane = tid & 31;
    const size_t rowBase = (size_t)blockIdx.x * 128;

    const int jm = lane >> 3;        // matrix index 0..3
    const int qm = lane & 7;         // row within matrix
    const int hb = jm & 1;           // x2 half select
    const int arow = wid * 16 + (jm >> 1) * 8 + qm;    // A row for this lane

    float acc[5][4];
    #pragma unroll
    for (int nt = 0; nt < 5; nt++)
        #pragma unroll
        for (int e = 0; e < 4; e++) acc[nt][e] = 0.f;

    for (int t = 0; t < STAGES - 1; t++)
        fill_stage(adj, rowBase, t, stage0 + t * STAGE_BYTES, tid);

    for (int kt = 0; kt < NT; kt++) {
        asm volatile("cp.async.wait_group %0;" :: "n"(STAGES - 2) : "memory");
        __syncthreads();

        // hoisted fill: overwrites buffer of tile kt-1 (ldsm'd before this sync);
        // cp.async issue overlaps this tile's ldsm/MMA work
        const int nxt = kt + STAGES - 1;
        if (nxt < NT)
            fill_stage(adj, rowBase, nxt, stage0 + (uint32_t)(nxt & (STAGES - 1)) * STAGE_BYTES, tid);

        const uint32_t sA = stage0 + (uint32_t)(kt & (STAGES - 1)) * STAGE_BYTES;
        const uint32_t sB = sA + ABYTES;

        #pragma unroll
        for (int s = 0; s < 4; s++) {
            const int ch  = 2 * s + (jm & 1);
            const int chx = 2 * s + hb;
            uint32_t a0, a1, a2, a3;
            ldsm_x4(a0, a1, a2, a3, sA + ((arow * 8 + (ch ^ (arow & 7))) << 4));
            uint32_t b[10];
            {
                const int nr0 = (jm >> 1) * 8 + qm;            // rows 0-15 -> tiles 0,1
                ldsm_x4(b[0], b[1], b[2], b[3],
                        sB + ((nr0 * 8 + (ch ^ (nr0 & 7))) << 4));
                const int nr1 = 16 + (jm >> 1) * 8 + qm;        // rows 16-31 -> tiles 2,3
                ldsm_x4(b[4], b[5], b[6], b[7],
                        sB + ((nr1 * 8 + (ch ^ (nr1 & 7))) << 4));
                const int nr2 = 32 + qm;                        // rows 32-39 -> tile 4
                ldsm_x2(b[8], b[9], sB + ((nr2 * 8 + (chx ^ (nr2 & 7))) << 4));
            }
            #pragma unroll
            for (int nt = 0; nt < 5; nt++)
                mma_tf32(acc[nt], a0, a2, a1, a3, b[2*nt], b[2*nt+1]);
        }
    }

    // degree = col 32 = tile 4 col offset 0 (lanes lane%4==0, elems 0 and 2)
    const int srcLane = lane & ~3;
    float dlo = __shfl_sync(0xffffffffu, acc[4][0], srcLane);
    float dhi = __shfl_sync(0xffffffffu, acc[4][2], srcLane);
    float rdlo = 1.0f / fmaxf(dlo, 1.0f);
    float rdhi = 1.0f / fmaxf(dhi, 1.0f);

    const size_t rlo = rowBase + (size_t)(wid * 16 + (lane >> 2));
    const size_t rhi = rlo + 8;
    const int coff = 2 * (lane & 3);
    #pragma unroll
    for (int nt = 0; nt < 4; nt++) {
        float2 olo = {acc[nt][0] * rdlo, acc[nt][1] * rdlo};
        float2 ohi = {acc[nt][2] * rdhi, acc[nt][3] * rdhi};
        *reinterpret_cast<float2*>(&g_agg[rlo * DDIM + 8 * nt + coff]) = olo;
        *reinterpret_cast<float2*>(&g_agg[rhi * DDIM + 8 * nt + coff]) = ohi;
    }
}

// ==================== Kernel 3: update MLP (round-7 warp-sliced, proven) ==========
__global__ __launch_bounds__(256) void upd_kernel(
    const float* __restrict__ states, const float* __restrict__ W1,
    const float* __restrict__ b1,     const float* __restrict__ W2,
    const float* __restrict__ b2,     float* __restrict__ out)
{
    extern __shared__ float sm[];
    float* sW1 = sm;                                       // [64][128]
    float* sW2 = sm + 2 * DDIM * HDIM;                     // [128][32]
    float* ex  = sm + 2 * DDIM * HDIM + HDIM * DDIM;       // [4][64][33]

    const int tid = threadIdx.x;
    for (int i = tid; i < 2 * DDIM * HDIM; i += 256) sW1[i] = W1[i];
    for (int i = tid; i < HDIM * DDIM; i += 256)     sW2[i] = W2[i];
    __syncthreads();

    const int wid  = tid >> 5, lane = tid & 31;
    const int g = wid >> 2, q = wid & 3;
    const int rowL = g * 32 + lane;
    const int row  = blockIdx.x * 64 + rowL;

    float x[2 * DDIM];
    const float4* sp = reinterpret_cast<const float4*>(states + (size_t)row * DDIM);
    const float4* gp = reinterpret_cast<const float4*>(g_agg  + (size_t)row * DDIM);
    #pragma unroll
    for (int j4 = 0; j4 < 8; j4++) {
        float4 v = sp[j4];
        x[4*j4+0] = v.x; x[4*j4+1] = v.y; x[4*j4+2] = v.z; x[4*j4+3] = v.w;
        float4 gg = gp[j4];
        x[DDIM+4*j4+0] = gg.x; x[DDIM+4*j4+1] = gg.y;
        x[DDIM+4*j4+2] = gg.z; x[DDIM+4*j4+3] = gg.w;
    }
    float hid[32];
    #pragma unroll
    for (int h4 = 0; h4 < 8; h4++) {
        float4 b = __ldg(reinterpret_cast<const float4*>(b1 + q * 32) + h4);
        hid[4*h4+0] = b.x; hid[4*h4+1] = b.y; hid[4*h4+2] = b.z; hid[4*h4+3] = b.w;
    }
    #pragma unroll
    for (int j = 0; j < 2 * DDIM; j++) {
        const float xj = x[j];
        #pragma unroll
        for (int h4 = 0; h4 < 8; h4++) {
            float4 w = *reinterpret_cast<const float4*>(&sW1[j * HDIM + q * 32 + 4 * h4]);
            hid[4*h4+0] += xj * w.x; hid[4*h4+1] += xj * w.y;
            hid[4*h4+2] += xj * w.z; hid[4*h4+3] += xj * w.w;
        }
    }
    float m[DDIM];
    #pragma unroll
    for (int d = 0; d < DDIM; d++) m[d] = 0.f;
    #pragma unroll
    for (int h = 0; h < 32; h++) {
        float r = fmaxf(hid[h], 0.f);
        #pragma unroll
        for (int d4 = 0; d4 < 8; d4++) {
            float4 w = *reinterpret_cast<const float4*>(&sW2[(q * 32 + h) * DDIM + 4 * d4]);
            m[4*d4+0] += r * w.x; m[4*d4+1] += r * w.y;
            m[4*d4+2] += r * w.z; m[4*d4+3] += r * w.w;
        }
    }
    #pragma unroll
    for (int d = 0; d < DDIM; d++)
        ex[(q * 64 + rowL) * EX_STRIDE + d] = m[d];
    __syncthreads();

    const int row2 = tid >> 2;
    const int dg   = (tid & 3) * 8;
    const size_t rowG = (size_t)blockIdx.x * 64 + row2;
    float o[8];
    #pragma unroll
    for (int e = 0; e < 8; e++) {
        const int d = dg + e;
        float v = __ldg(&b2[d]);
        #pragma unroll
        for (int qq = 0; qq < 4; qq++)
            v += ex[(qq * 64 + row2) * EX_STRIDE + d];
        o[e] = v;
    }
    float4* op = reinterpret_cast<float4*>(out + rowG * DDIM + dg);
    op[0] = make_float4(o[0], o[1], o[2], o[3]);
    op[1] = make_float4(o[4], o[5], o[6], o[7]);
}

// ==================== launch ====================
extern "C" void kernel_launch(void* const* d_in, const int* in_sizes, int n_in,
                              void* d_out, int out_size)
{
    const float* states = (const float*)d_in[0];
    const float* adj    = (const float*)d_in[1];
    const float* mW1    = (const float*)d_in[2];
    const float* mb1    = (const float*)d_in[3];
    const float* mW2    = (const float*)d_in[4];
    const float* mb2    = (const float*)d_in[5];
    const float* uW1    = (const float*)d_in[6];
    const float* ub1    = (const float*)d_in[7];
    const float* uW2    = (const float*)d_in[8];
    const float* ub2    = (const float*)d_in[9];
    float* out = (float*)d_out;

    cudaFuncSetAttribute(agg_kernel, cudaFuncAttributeMaxDynamicSharedMemorySize, SMEM_TOTAL);
    cudaFuncSetAttribute(upd_kernel, cudaFuncAttributeMaxDynamicSharedMemorySize, UPD_SMEM);

    msg_kernel<<<NROWS / 128, 128>>>(states, mW1, mb1, mW2, mb2);
    agg_kernel<<<NROWS / 128, 256, SMEM_TOTAL>>>(adj);
    upd_kernel<<<NROWS / 64, 256, UPD_SMEM>>>(states, uW1, ub1, uW2, ub2, out);
}

// round 10
// speedup vs baseline: 1.7104x; 1.0497x over previous
#include <cuda_runtime.h>
#include <cstdint>

#define NROWS 16384
#define DDIM  32
#define HDIM  128
#define BK    32                 // K floats per sub-tile -> 128B rows
#define BN    40                 // smem B rows per sub-tile (33 live + 7 pad)
#define STAGES 4                 // each stage = 2 sub-tiles (64 k-floats)
#define NT2   (NROWS / (2 * BK)) // 256 double-tiles
#define SUBA  (128 * 128)        // 16384 per A sub-tile
#define SUBB  (BN * 128)         // 5120 per B sub-tile
#define STAGE_BYTES (2 * SUBA + 2 * SUBB)           // 43008
#define SMEM_TOTAL  (1024 + STAGES * STAGE_BYTES)   // 173056

// update MLP smem
#define EX_STRIDE 33
#define EX_BYTES  (4 * 64 * EX_STRIDE * 4)
#define UPD_SMEM  (2 * DDIM * HDIM * 4 + HDIM * DDIM * 4 + EX_BYTES)  // 82944

// device scratch
__device__ float g_msgB[BN * NROWS];   // [col][k]; cols0-31 tf32 msg, col32=1
__device__ float g_agg [NROWS * DDIM];

// ---------------- PTX helpers ----------------
__device__ __forceinline__ void cp16(uint32_t dst, const void* src) {
    asm volatile("cp.async.cg.shared.global [%0], [%1], 16;" :: "r"(dst), "l"(src) : "memory");
}
__device__ __forceinline__ float tf32_rna(float x) {
    uint32_t r;
    asm("cvt.rna.tf32.f32 %0, %1;" : "=r"(r) : "f"(x));
    return __uint_as_float(r);
}
__device__ __forceinline__ void ldsm_x4(uint32_t& r0, uint32_t& r1, uint32_t& r2, uint32_t& r3,
                                        uint32_t addr) {
    asm volatile("ldmatrix.sync.aligned.m8n8.x4.shared.b16 {%0,%1,%2,%3}, [%4];"
                 : "=r"(r0), "=r"(r1), "=r"(r2), "=r"(r3) : "r"(addr));
}
__device__ __forceinline__ void ldsm_x2(uint32_t& r0, uint32_t& r1, uint32_t addr) {
    asm volatile("ldmatrix.sync.aligned.m8n8.x2.shared.b16 {%0,%1}, [%2];"
                 : "=r"(r0), "=r"(r1) : "r"(addr));
}
__device__ __forceinline__ void mma_tf32(float* c, uint32_t a0, uint32_t a1,
                                         uint32_t a2, uint32_t a3,
                                         uint32_t b0, uint32_t b1) {
    asm volatile(
        "mma.sync.aligned.m16n8k8.row.col.f32.tf32.tf32.f32 "
        "{%0,%1,%2,%3}, {%4,%5,%6,%7}, {%8,%9}, {%0,%1,%2,%3};"
        : "+f"(c[0]), "+f"(c[1]), "+f"(c[2]), "+f"(c[3])
        : "r"(a0), "r"(a1), "r"(a2), "r"(a3), "r"(b0), "r"(b1));
}

// ==================== Kernel 1: message MLP (round-9 proven) ====================
__global__ __launch_bounds__(128) void msg_kernel(
    const float* __restrict__ states, const float* __restrict__ W1,
    const float* __restrict__ b1,     const float* __restrict__ W2,
    const float* __restrict__ b2)
{
    __shared__ float sW1[DDIM * HDIM];
    __shared__ float sW2[HDIM * DDIM];
    const int tid = threadIdx.x;
    for (int i = tid; i < DDIM * HDIM; i += 128) sW1[i] = W1[i];
    for (int i = tid; i < HDIM * DDIM; i += 128) sW2[i] = W2[i];
    __syncthreads();

    const int row = blockIdx.x * 128 + tid;
    float s[DDIM];
    const float4* sp = reinterpret_cast<const float4*>(states + (size_t)row * DDIM);
    #pragma unroll
    for (int j4 = 0; j4 < DDIM / 4; j4++) {
        float4 v = sp[j4];
        s[4*j4+0] = v.x; s[4*j4+1] = v.y; s[4*j4+2] = v.z; s[4*j4+3] = v.w;
    }
    float m[DDIM];
    #pragma unroll
    for (int d = 0; d < DDIM; d++) m[d] = __ldg(&b2[d]);

    #pragma unroll 4
    for (int hg = 0; hg < HDIM / 4; hg++) {
        float4 hid = __ldg(reinterpret_cast<const float4*>(b1) + hg);
        #pragma unroll
        for (int j = 0; j < DDIM; j++) {
            float4 w = *reinterpret_cast<const float4*>(&sW1[j * HDIM + 4 * hg]);
            hid.x += s[j] * w.x; hid.y += s[j] * w.y;
            hid.z += s[j] * w.z; hid.w += s[j] * w.w;
        }
        float rr[4] = {fmaxf(hid.x, 0.f), fmaxf(hid.y, 0.f),
                       fmaxf(hid.z, 0.f), fmaxf(hid.w, 0.f)};
        #pragma unroll
        for (int e = 0; e < 4; e++) {
            float r = rr[e];
            #pragma unroll
            for (int d4 = 0; d4 < DDIM / 4; d4++) {
                float4 w = *reinterpret_cast<const float4*>(&sW2[(4*hg+e) * DDIM + 4*d4]);
                m[4*d4+0] += r * w.x; m[4*d4+1] += r * w.y;
                m[4*d4+2] += r * w.z; m[4*d4+3] += r * w.w;
            }
        }
    }
    #pragma unroll
    for (int d = 0; d < DDIM; d++)
        g_msgB[(size_t)d * NROWS + row] = tf32_rna(m[d]);
    g_msgB[(size_t)32 * NROWS + row] = 1.0f;          // degree column
}

// ==================== Kernel 2: tf32 aggregation, double-tile stages ==========
// stage layout: [A0 16K][A1 16K][B0 5K][B1 5K]
__device__ __forceinline__ void fill_stage2(const float* __restrict__ adj, size_t rowBase,
                                            int t2, uint32_t stage, int tid)
{
    const float* aSrc = adj + rowBase * NROWS + (size_t)t2 * (2 * BK);
    #pragma unroll
    for (int i = 0; i < 8; i++) {                     // A: 2048 16B chunks
        int c = tid + 256 * i;
        int sub = c >> 10, w = c & 1023;
        int r = w >> 3, k4 = w & 7;
        uint32_t dst = stage + sub * SUBA + ((r * 8 + (k4 ^ (r & 7))) << 4);
        cp16(dst, aSrc + (size_t)r * NROWS + sub * BK + (k4 << 2));
    }
    #pragma unroll
    for (int i = 0; i < 3; i++) {                     // B: 528 chunks (2 x 33 rows)
        int c = tid + 256 * i;
        if (i < 2 || c < 528) {
            int sub = c >= 264, w = c - 264 * sub;
            int r = w >> 3, k4 = w & 7;
            uint32_t dst = stage + 2 * SUBA + sub * SUBB + ((r * 8 + (k4 ^ (r & 7))) << 4);
            cp16(dst, g_msgB + (size_t)r * NROWS + (size_t)t2 * (2 * BK) + sub * BK + (k4 << 2));
        }
    }
    asm volatile("cp.async.commit_group;" ::: "memory");
}

__global__ __launch_bounds__(256, 1) void agg_kernel(const float* __restrict__ adj)
{
    extern __shared__ char smem[];
    uint32_t sraw = (uint32_t)__cvta_generic_to_shared(smem);
    const uint32_t stage0 = (sraw + 1023u) & ~1023u;

    const int tid  = threadIdx.x;
    const int wid  = tid >> 5;
    const int lane = tid & 31;
    const size_t rowBase = (size_t)blockIdx.x * 128;

    const int jm = lane >> 3;        // matrix index 0..3
    const int qm = lane & 7;         // row within matrix
    const int hb = jm & 1;           // x2 half select
    const int arow = wid * 16 + (jm >> 1) * 8 + qm;    // A row for this lane

    float acc[5][4];
    #pragma unroll
    for (int nt = 0; nt < 5; nt++)
        #pragma unroll
        for (int e = 0; e < 4; e++) acc[nt][e] = 0.f;

    for (int t = 0; t < STAGES - 1; t++)
        fill_stage2(adj, rowBase, t, stage0 + t * STAGE_BYTES, tid);

    for (int kt2 = 0; kt2 < NT2; kt2++) {
        asm volatile("cp.async.wait_group %0;" :: "n"(STAGES - 2) : "memory");
        __syncthreads();

        const int nxt = kt2 + STAGES - 1;
        if (nxt < NT2)
            fill_stage2(adj, rowBase, nxt,
                        stage0 + (uint32_t)(nxt & (STAGES - 1)) * STAGE_BYTES, tid);

        const uint32_t stg = stage0 + (uint32_t)(kt2 & (STAGES - 1)) * STAGE_BYTES;

        #pragma unroll
        for (int sub = 0; sub < 2; sub++) {
            const uint32_t sA = stg + sub * SUBA;
            const uint32_t sB = stg + 2 * SUBA + sub * SUBB;
            #pragma unroll
            for (int s = 0; s < 4; s++) {
                const int ch  = 2 * s + (jm & 1);
                const int chx = 2 * s + hb;
                uint32_t a0, a1, a2, a3;
                ldsm_x4(a0, a1, a2, a3, sA + ((arow * 8 + (ch ^ (arow & 7))) << 4));
                uint32_t b[10];
                {
                    const int nr0 = (jm >> 1) * 8 + qm;            // tiles 0,1
                    ldsm_x4(b[0], b[1], b[2], b[3],
                            sB + ((nr0 * 8 + (ch ^ (nr0 & 7))) << 4));
                    const int nr1 = 16 + (jm >> 1) * 8 + qm;        // tiles 2,3
                    ldsm_x4(b[4], b[5], b[6], b[7],
                            sB + ((nr1 * 8 + (ch ^ (nr1 & 7))) << 4));
                    const int nr2 = 32 + qm;                        // tile 4 (degree)
                    ldsm_x2(b[8], b[9], sB + ((nr2 * 8 + (chx ^ (nr2 & 7))) << 4));
                }
                #pragma unroll
                for (int nt = 0; nt < 5; nt++)
                    mma_tf32(acc[nt], a0, a2, a1, a3, b[2*nt], b[2*nt+1]);
            }
        }
    }

    // degree = col 32 = tile 4 col offset 0 (lanes lane%4==0, elems 0 and 2)
    const int srcLane = lane & ~3;
    float dlo = __shfl_sync(0xffffffffu, acc[4][0], srcLane);
    float dhi = __shfl_sync(0xffffffffu, acc[4][2], srcLane);
    float rdlo = 1.0f / fmaxf(dlo, 1.0f);
    float rdhi = 1.0f / fmaxf(dhi, 1.0f);

    const size_t rlo = rowBase + (size_t)(wid * 16 + (lane >> 2));
    const size_t rhi = rlo + 8;
    const int coff = 2 * (lane & 3);
    #pragma unroll
    for (int nt = 0; nt < 4; nt++) {
        float2 olo = {acc[nt][0] * rdlo, acc[nt][1] * rdlo};
        float2 ohi = {acc[nt][2] * rdhi, acc[nt][3] * rdhi};
        *reinterpret_cast<float2*>(&g_agg[rlo * DDIM + 8 * nt + coff]) = olo;
        *reinterpret_cast<float2*>(&g_agg[rhi * DDIM + 8 * nt + coff]) = ohi;
    }
}

// ==================== Kernel 3: update MLP (round-7 warp-sliced, proven) ==========
__global__ __launch_bounds__(256) void upd_kernel(
    const float* __restrict__ states, const float* __restrict__ W1,
    const float* __restrict__ b1,     const float* __restrict__ W2,
    const float* __restrict__ b2,     float* __restrict__ out)
{
    extern __shared__ float sm[];
    float* sW1 = sm;                                       // [64][128]
    float* sW2 = sm + 2 * DDIM * HDIM;                     // [128][32]
    float* ex  = sm + 2 * DDIM * HDIM + HDIM * DDIM;       // [4][64][33]

    const int tid = threadIdx.x;
    for (int i = tid; i < 2 * DDIM * HDIM; i += 256) sW1[i] = W1[i];
    for (int i = tid; i < HDIM * DDIM; i += 256)     sW2[i] = W2[i];
    __syncthreads();

    const int wid  = tid >> 5, lane = tid & 31;
    const int g = wid >> 2, q = wid & 3;
    const int rowL = g * 32 + lane;
    const int row  = blockIdx.x * 64 + rowL;

    float x[2 * DDIM];
    const float4* sp = reinterpret_cast<const float4*>(states + (size_t)row * DDIM);
    const float4* gp = reinterpret_cast<const float4*>(g_agg  + (size_t)row * DDIM);
    #pragma unroll
    for (int j4 = 0; j4 < 8; j4++) {
        float4 v = sp[j4];
        x[4*j4+0] = v.x; x[4*j4+1] = v.y; x[4*j4+2] = v.z; x[4*j4+3] = v.w;
        float4 gg = gp[j4];
        x[DDIM+4*j4+0] = gg.x; x[DDIM+4*j4+1] = gg.y;
        x[DDIM+4*j4+2] = gg.z; x[DDIM+4*j4+3] = gg.w;
    }
    float hid[32];
    #pragma unroll
    for (int h4 = 0; h4 < 8; h4++) {
        float4 b = __ldg(reinterpret_cast<const float4*>(b1 + q * 32) + h4);
        hid[4*h4+0] = b.x; hid[4*h4+1] = b.y; hid[4*h4+2] = b.z; hid[4*h4+3] = b.w;
    }
    #pragma unroll
    for (int j = 0; j < 2 * DDIM; j++) {
        const float xj = x[j];
        #pragma unroll
        for (int h4 = 0; h4 < 8; h4++) {
            float4 w = *reinterpret_cast<const float4*>(&sW1[j * HDIM + q * 32 + 4 * h4]);
            hid[4*h4+0] += xj * w.x; hid[4*h4+1] += xj * w.y;
            hid[4*h4+2] += xj * w.z; hid[4*h4+3] += xj * w.w;
        }
    }
    float m[DDIM];
    #pragma unroll
    for (int d = 0; d < DDIM; d++) m[d] = 0.f;
    #pragma unroll
    for (int h = 0; h < 32; h++) {
        float r = fmaxf(hid[h], 0.f);
        #pragma unroll
        for (int d4 = 0; d4 < 8; d4++) {
            float4 w = *reinterpret_cast<const float4*>(&sW2[(q * 32 + h) * DDIM + 4 * d4]);
            m[4*d4+0] += r * w.x; m[4*d4+1] += r * w.y;
            m[4*d4+2] += r * w.z; m[4*d4+3] += r * w.w;
        }
    }
    #pragma unroll
    for (int d = 0; d < DDIM; d++)
        ex[(q * 64 + rowL) * EX_STRIDE + d] = m[d];
    __syncthreads();

    const int row2 = tid >> 2;
    const int dg   = (tid & 3) * 8;
    const size_t rowG = (size_t)blockIdx.x * 64 + row2;
    float o[8];
    #pragma unroll
    for (int e = 0; e < 8; e++) {
        const int d = dg + e;
        float v = __ldg(&b2[d]);
        #pragma unroll
        for (int qq = 0; qq < 4; qq++)
            v += ex[(qq * 64 + row2) * EX_STRIDE + d];
        o[e] = v;
    }
    float4* op = reinterpret_cast<float4*>(out + rowG * DDIM + dg);
    op[0] = make_float4(o[0], o[1], o[2], o[3]);
    op[1] = make_float4(o[4], o[5], o[6], o[7]);
}

// ==================== launch ====================
extern "C" void kernel_launch(void* const* d_in, const int* in_sizes, int n_in,
                              void* d_out, int out_size)
{
    const float* states = (const float*)d_in[0];
    const float* adj    = (const float*)d_in[1];
    const float* mW1    = (const float*)d_in[2];
    const float* mb1    = (const float*)d_in[3];
    const float* mW2    = (const float*)d_in[4];
    const float* mb2    = (const float*)d_in[5];
    const float* uW1    = (const float*)d_in[6];
    const float* ub1    = (const float*)d_in[7];
    const float* uW2    = (const float*)d_in[8];
    const float* ub2    = (const float*)d_in[9];
    float* out = (float*)d_out;

    cudaFuncSetAttribute(agg_kernel, cudaFuncAttributeMaxDynamicSharedMemorySize, SMEM_TOTAL);
    cudaFuncSetAttribute(upd_kernel, cudaFuncAttributeMaxDynamicSharedMemorySize, UPD_SMEM);

    msg_kernel<<<NROWS / 128, 128>>>(states, mW1, mb1, mW2, mb2);
    agg_kernel<<<NROWS / 128, 256, SMEM_TOTAL>>>(adj);
    upd_kernel<<<NROWS / 64, 256, UPD_SMEM>>>(states, uW1, ub1, uW2, ub2, out);
}